// round 7
// baseline (speedup 1.0000x reference)
#include <cuda_runtime.h>
#include <mma.h>
#include <math.h>

using namespace nvcuda;

#define NT 4096
#define DD 512
#define BM 128
#define BN 128
#define BK 16

// ---------------- scratch (no cudaMalloc allowed) ----------------
// Q_r,K_r,V_r,Q_l,K_l,V_l
__device__ float g_QKV[6][NT * DD];          // 48 MB
__device__ float g_S2 [2][(size_t)NT * NT];  // 128 MB
__device__ float g_X2 [2][NT * DD];          // 16 MB
__device__ float g_Xn2[2][NT * DD];          // 16 MB
__device__ float g_H2 [2][NT * DD];          // 16 MB

// ---------------- pointer bundles (passed by value) ----------------
struct GemmB {                // batched GEMM operands, indexed by blockIdx.z
    const float* A[6];
    const float* B[6];
    float*       C[6];
    const float* biasVec[6];  // optional per-z epilogue bias (may be null)
};
struct LnB {
    const float* X[2];
    const float* resid[2];
    const float* biasVec[2];  // may be null
    const float* g[2];
    const float* b[2];
    float*       out[2];
};

// ---------------- helpers ----------------
__device__ __forceinline__ void split_store(float x, float* hp, float* lp) {
    float h = wmma::__float_to_tf32(x);
    *hp = h;
    *lp = wmma::__float_to_tf32(x - h);
}

__device__ __forceinline__ float blockReduceSum(float v) {
    __shared__ float sh[32];
    const int lane = threadIdx.x & 31;
    const int warp = threadIdx.x >> 5;
    const int nw = blockDim.x >> 5;
#pragma unroll
    for (int o = 16; o > 0; o >>= 1) v += __shfl_xor_sync(0xffffffffu, v, o);
    __syncthreads();
    if (lane == 0) sh[warp] = v;
    __syncthreads();
    float s = (threadIdx.x < nw) ? sh[threadIdx.x] : 0.0f;
#pragma unroll
    for (int o = 16; o > 0; o >>= 1) s += __shfl_xor_sync(0xffffffffu, s, o);
    if (threadIdx.x == 0) sh[0] = s;
    __syncthreads();
    return sh[0];
}

__device__ __forceinline__ float blockReduceMax(float v) {
    __shared__ float sh[32];
    const int lane = threadIdx.x & 31;
    const int warp = threadIdx.x >> 5;
    const int nw = blockDim.x >> 5;
#pragma unroll
    for (int o = 16; o > 0; o >>= 1) v = fmaxf(v, __shfl_xor_sync(0xffffffffu, v, o));
    __syncthreads();
    if (lane == 0) sh[warp] = v;
    __syncthreads();
    float s = (threadIdx.x < nw) ? sh[threadIdx.x] : -3.402823466e38f;
#pragma unroll
    for (int o = 16; o > 0; o >>= 1) s = fmaxf(s, __shfl_xor_sync(0xffffffffu, s, o));
    if (threadIdx.x == 0) sh[0] = s;
    __syncthreads();
    return sh[0];
}

// ================= batched GEMM NN (split-tf32, double-buffered) =================
// C[z] = A[z][MxK] @ B[z][KxN] (+biasVec[z]) (relu), M=4096, N=512.
// 128x128 tile, BK=16, 256 thr, 8 warps (4x2), warp tile 32x64, wmma 16x16x8,
// hi/lo split => 3 MMAs/product.
// Dynamic smem: Ah/Al[2][128][20], Bh/Bl[2][16][132]  (74752 B)
#define NN_SMEM_FLOATS (2*128*20*2 + 2*16*132*2)
#define NN_SMEM_BYTES (NN_SMEM_FLOATS * 4)

__global__ __launch_bounds__(256)
void gemm_nn_tf32(GemmB p, int K, int doRelu)
{
    const int N = DD;
    const float* __restrict__ A = p.A[blockIdx.z];
    const float* __restrict__ B = p.B[blockIdx.z];
    float* __restrict__ C = p.C[blockIdx.z];
    const float* __restrict__ biasVec = p.biasVec[blockIdx.z];

    extern __shared__ float sm[];
    float (*Ah)[128][20] = (float(*)[128][20])(sm);
    float (*Al)[128][20] = (float(*)[128][20])(sm + 2*128*20);
    float (*Bh)[16][132] = (float(*)[16][132])(sm + 4*128*20);
    float (*Bl)[16][132] = (float(*)[16][132])(sm + 4*128*20 + 2*16*132);

    const int tid = threadIdx.x;
    const int bm = blockIdx.y * BM;
    const int bn = blockIdx.x * BN;
    const int warp = tid >> 5;
    const int wm = (warp & 3) * 32;
    const int wn = (warp >> 2) * 64;

    wmma::fragment<wmma::accumulator, 16, 16, 8, float> acc[2][4];
#pragma unroll
    for (int i = 0; i < 2; i++)
#pragma unroll
        for (int j = 0; j < 4; j++) wmma::fill_fragment(acc[i][j], 0.0f);

    const int ar = tid >> 2;            // 0..63
    const int ac = (tid & 3) << 2;      // 0,4,8,12
    const int br = tid >> 5;            // 0..7
    const int bc = (tid & 31) << 2;     // 0..124

    const float* Abase = A + (size_t)(bm + ar) * K + ac;
    const float* Bbase = B + (size_t)br * N + bn + bc;
    const size_t AstepRow = (size_t)64 * K;
    const size_t BstepRow = (size_t)8 * N;

    const int ntiles = K / BK;

    float4 aR[2], bR[2];
#pragma unroll
    for (int s = 0; s < 2; s++) {
        aR[s] = *(const float4*)(Abase + s * AstepRow);
        bR[s] = *(const float4*)(Bbase + s * BstepRow);
    }
#pragma unroll
    for (int s = 0; s < 2; s++) {
        const int r = ar + s * 64;
        split_store(aR[s].x, &Ah[0][r][ac+0], &Al[0][r][ac+0]);
        split_store(aR[s].y, &Ah[0][r][ac+1], &Al[0][r][ac+1]);
        split_store(aR[s].z, &Ah[0][r][ac+2], &Al[0][r][ac+2]);
        split_store(aR[s].w, &Ah[0][r][ac+3], &Al[0][r][ac+3]);
        const int rb = br + s * 8;
        split_store(bR[s].x, &Bh[0][rb][bc+0], &Bl[0][rb][bc+0]);
        split_store(bR[s].y, &Bh[0][rb][bc+1], &Bl[0][rb][bc+1]);
        split_store(bR[s].z, &Bh[0][rb][bc+2], &Bl[0][rb][bc+2]);
        split_store(bR[s].w, &Bh[0][rb][bc+3], &Bl[0][rb][bc+3]);
    }
    __syncthreads();

    for (int t = 0; t < ntiles; ++t) {
        const int cur = t & 1;
        const int nxt = cur ^ 1;
        if (t + 1 < ntiles) {
            const int koff = (t + 1) * BK;
#pragma unroll
            for (int s = 0; s < 2; s++) {
                aR[s] = *(const float4*)(Abase + s * AstepRow + koff);
                bR[s] = *(const float4*)(Bbase + s * BstepRow + (size_t)koff * N);
            }
        }

#pragma unroll
        for (int kk = 0; kk < BK; kk += 8) {
            wmma::fragment<wmma::matrix_a, 16, 16, 8, wmma::precision::tf32, wmma::row_major> aH[2], aL[2];
            wmma::fragment<wmma::matrix_b, 16, 16, 8, wmma::precision::tf32, wmma::row_major> bH[4], bL[4];
#pragma unroll
            for (int i = 0; i < 2; i++) {
                wmma::load_matrix_sync(aH[i], &Ah[cur][wm + i * 16][kk], 20);
                wmma::load_matrix_sync(aL[i], &Al[cur][wm + i * 16][kk], 20);
            }
#pragma unroll
            for (int j = 0; j < 4; j++) {
                wmma::load_matrix_sync(bH[j], &Bh[cur][kk][wn + j * 16], 132);
                wmma::load_matrix_sync(bL[j], &Bl[cur][kk][wn + j * 16], 132);
            }
#pragma unroll
            for (int i = 0; i < 2; i++)
#pragma unroll
                for (int j = 0; j < 4; j++) {
                    wmma::mma_sync(acc[i][j], aH[i], bH[j], acc[i][j]);
                    wmma::mma_sync(acc[i][j], aH[i], bL[j], acc[i][j]);
                    wmma::mma_sync(acc[i][j], aL[i], bH[j], acc[i][j]);
                }
        }

        if (t + 1 < ntiles) {
#pragma unroll
            for (int s = 0; s < 2; s++) {
                const int r = ar + s * 64;
                split_store(aR[s].x, &Ah[nxt][r][ac+0], &Al[nxt][r][ac+0]);
                split_store(aR[s].y, &Ah[nxt][r][ac+1], &Al[nxt][r][ac+1]);
                split_store(aR[s].z, &Ah[nxt][r][ac+2], &Al[nxt][r][ac+2]);
                split_store(aR[s].w, &Ah[nxt][r][ac+3], &Al[nxt][r][ac+3]);
                const int rb = br + s * 8;
                split_store(bR[s].x, &Bh[nxt][rb][bc+0], &Bl[nxt][rb][bc+0]);
                split_store(bR[s].y, &Bh[nxt][rb][bc+1], &Bl[nxt][rb][bc+1]);
                split_store(bR[s].z, &Bh[nxt][rb][bc+2], &Bl[nxt][rb][bc+2]);
                split_store(bR[s].w, &Bh[nxt][rb][bc+3], &Bl[nxt][rb][bc+3]);
            }
            __syncthreads();
        }
    }

#pragma unroll
    for (int i = 0; i < 2; i++)
#pragma unroll
        for (int j = 0; j < 4; j++)
            wmma::store_matrix_sync(C + (size_t)(bm + wm + i * 16) * N + bn + wn + j * 16,
                                    acc[i][j], N, wmma::mem_row_major);

    // Fused epilogue: bias (+relu) applied to the freshly-stored C tile while
    // it is still L1/L2 resident. Fragment layout-agnostic (post-store pass).
    if (biasVec) {
        __syncthreads();
        const int er = tid >> 1;               // 0..127
        const int ec = (tid & 1) * 64;         // 0 or 64
        float* crow = C + (size_t)(bm + er) * N + bn + ec;
        const float* bv = biasVec + bn + ec;
#pragma unroll
        for (int c = 0; c < 64; c += 4) {
            float4 v = *(const float4*)(crow + c);
            float4 b = *(const float4*)(bv + c);
            v.x += b.x; v.y += b.y; v.z += b.z; v.w += b.w;
            if (doRelu) {
                v.x = fmaxf(v.x, 0.0f); v.y = fmaxf(v.y, 0.0f);
                v.z = fmaxf(v.z, 0.0f); v.w = fmaxf(v.w, 0.0f);
            }
            *(float4*)(crow + c) = v;
        }
    }
}

// ================= batched GEMM NT (split-tf32, double-buffered) =================
// C[z] = scale * A[z][MxK] @ B[z][NxK]^T, M=N=4096, K=512.
// Dynamic smem: Ah/Al/Bh/Bl[2][128][20]  (81920 B)
#define NTS_SMEM_FLOATS (4*2*128*20)
#define NTS_SMEM_BYTES (NTS_SMEM_FLOATS * 4)

__global__ __launch_bounds__(256)
void gemm_nt_tf32(GemmB p, int K, float scale)
{
    const int N = NT;
    const float* __restrict__ A = p.A[blockIdx.z];
    const float* __restrict__ B = p.B[blockIdx.z];
    float* __restrict__ C = p.C[blockIdx.z];

    extern __shared__ float sm[];
    float (*Ah)[128][20] = (float(*)[128][20])(sm);
    float (*Al)[128][20] = (float(*)[128][20])(sm + 2*128*20);
    float (*Bh)[128][20] = (float(*)[128][20])(sm + 4*128*20);
    float (*Bl)[128][20] = (float(*)[128][20])(sm + 6*128*20);

    const int tid = threadIdx.x;
    const int bm = blockIdx.y * BM;
    const int bn = blockIdx.x * BN;
    const int warp = tid >> 5;
    const int wm = (warp & 3) * 32;
    const int wn = (warp >> 2) * 64;

    wmma::fragment<wmma::accumulator, 16, 16, 8, float> acc[2][4];
#pragma unroll
    for (int i = 0; i < 2; i++)
#pragma unroll
        for (int j = 0; j < 4; j++) wmma::fill_fragment(acc[i][j], 0.0f);

    const int ar = tid >> 2;            // 0..63
    const int ac = (tid & 3) << 2;      // 0,4,8,12

    const float* Abase = A + (size_t)(bm + ar) * K + ac;
    const float* Bbase = B + (size_t)(bn + ar) * K + ac;
    const size_t stepRow = (size_t)64 * K;

    const int ntiles = K / BK;

    float4 aR[2], bR[2];
#pragma unroll
    for (int s = 0; s < 2; s++) {
        aR[s] = *(const float4*)(Abase + s * stepRow);
        bR[s] = *(const float4*)(Bbase + s * stepRow);
    }
#pragma unroll
    for (int s = 0; s < 2; s++) {
        const int r = ar + s * 64;
        split_store(aR[s].x, &Ah[0][r][ac+0], &Al[0][r][ac+0]);
        split_store(aR[s].y, &Ah[0][r][ac+1], &Al[0][r][ac+1]);
        split_store(aR[s].z, &Ah[0][r][ac+2], &Al[0][r][ac+2]);
        split_store(aR[s].w, &Ah[0][r][ac+3], &Al[0][r][ac+3]);
        split_store(bR[s].x, &Bh[0][r][ac+0], &Bl[0][r][ac+0]);
        split_store(bR[s].y, &Bh[0][r][ac+1], &Bl[0][r][ac+1]);
        split_store(bR[s].z, &Bh[0][r][ac+2], &Bl[0][r][ac+2]);
        split_store(bR[s].w, &Bh[0][r][ac+3], &Bl[0][r][ac+3]);
    }
    __syncthreads();

    for (int t = 0; t < ntiles; ++t) {
        const int cur = t & 1;
        const int nxt = cur ^ 1;
        if (t + 1 < ntiles) {
            const int koff = (t + 1) * BK;
#pragma unroll
            for (int s = 0; s < 2; s++) {
                aR[s] = *(const float4*)(Abase + s * stepRow + koff);
                bR[s] = *(const float4*)(Bbase + s * stepRow + koff);
            }
        }

#pragma unroll
        for (int kk = 0; kk < BK; kk += 8) {
            wmma::fragment<wmma::matrix_a, 16, 16, 8, wmma::precision::tf32, wmma::row_major> aH[2], aL[2];
            wmma::fragment<wmma::matrix_b, 16, 16, 8, wmma::precision::tf32, wmma::col_major> bH[4], bL[4];
#pragma unroll
            for (int i = 0; i < 2; i++) {
                wmma::load_matrix_sync(aH[i], &Ah[cur][wm + i * 16][kk], 20);
                wmma::load_matrix_sync(aL[i], &Al[cur][wm + i * 16][kk], 20);
            }
#pragma unroll
            for (int j = 0; j < 4; j++) {
                wmma::load_matrix_sync(bH[j], &Bh[cur][wn + j * 16][kk], 20);
                wmma::load_matrix_sync(bL[j], &Bl[cur][wn + j * 16][kk], 20);
            }
#pragma unroll
            for (int i = 0; i < 2; i++)
#pragma unroll
                for (int j = 0; j < 4; j++) {
                    wmma::mma_sync(acc[i][j], aH[i], bH[j], acc[i][j]);
                    wmma::mma_sync(acc[i][j], aH[i], bL[j], acc[i][j]);
                    wmma::mma_sync(acc[i][j], aL[i], bH[j], acc[i][j]);
                }
        }

        if (t + 1 < ntiles) {
#pragma unroll
            for (int s = 0; s < 2; s++) {
                const int r = ar + s * 64;
                split_store(aR[s].x, &Ah[nxt][r][ac+0], &Al[nxt][r][ac+0]);
                split_store(aR[s].y, &Ah[nxt][r][ac+1], &Al[nxt][r][ac+1]);
                split_store(aR[s].z, &Ah[nxt][r][ac+2], &Al[nxt][r][ac+2]);
                split_store(aR[s].w, &Ah[nxt][r][ac+3], &Al[nxt][r][ac+3]);
                split_store(bR[s].x, &Bh[nxt][r][ac+0], &Bl[nxt][r][ac+0]);
                split_store(bR[s].y, &Bh[nxt][r][ac+1], &Bl[nxt][r][ac+1]);
                split_store(bR[s].z, &Bh[nxt][r][ac+2], &Bl[nxt][r][ac+2]);
                split_store(bR[s].w, &Bh[nxt][r][ac+3], &Bl[nxt][r][ac+3]);
            }
            __syncthreads();
        }
    }

#pragma unroll
    for (int i = 0; i < 2; i++)
#pragma unroll
        for (int j = 0; j < 4; j++) {
#pragma unroll
            for (int t = 0; t < acc[i][j].num_elements; t++) acc[i][j].x[t] *= scale;
            wmma::store_matrix_sync(C + (size_t)(bm + wm + i * 16) * N + bn + wn + j * 16,
                                    acc[i][j], N, wmma::mem_row_major);
        }
}

// ------- bias(+transform) + softmax, both branches: grid (4096 rows, 2 branches) -------
// z=0: bias = exp(-0.005*De^2); z=1: bias = Dg.  512 threads, 8 elems/thread.
__global__ void softmax_bias(float* __restrict__ S0, float* __restrict__ S1,
                             const float* __restrict__ De, const float* __restrict__ Dg)
{
    const int row = blockIdx.x;
    const int expMode = (blockIdx.y == 0);   // uniform per block
    float* p = (expMode ? S0 : S1) + (size_t)row * NT;
    const float* bp = (expMode ? De : Dg) + (size_t)row * NT;
    const int tid = threadIdx.x;
    float4 v[2];
    float mx = -3.402823466e38f;
#pragma unroll
    for (int i = 0; i < 2; i++) {
        v[i] = ((const float4*)p)[i * 512 + tid];
        float4 b = ((const float4*)bp)[i * 512 + tid];
        if (expMode) {
            v[i].x += __expf(b.x * b.x * (-0.005f));
            v[i].y += __expf(b.y * b.y * (-0.005f));
            v[i].z += __expf(b.z * b.z * (-0.005f));
            v[i].w += __expf(b.w * b.w * (-0.005f));
        } else {
            v[i].x += b.x; v[i].y += b.y; v[i].z += b.z; v[i].w += b.w;
        }
        mx = fmaxf(mx, fmaxf(fmaxf(v[i].x, v[i].y), fmaxf(v[i].z, v[i].w)));
    }
    mx = blockReduceMax(mx);
    float s = 0.0f;
#pragma unroll
    for (int i = 0; i < 2; i++) {
        v[i].x = __expf(v[i].x - mx);
        v[i].y = __expf(v[i].y - mx);
        v[i].z = __expf(v[i].z - mx);
        v[i].w = __expf(v[i].w - mx);
        s += v[i].x + v[i].y + v[i].z + v[i].w;
    }
    s = blockReduceSum(s);
    const float inv = 1.0f / s;
#pragma unroll
    for (int i = 0; i < 2; i++) {
        v[i].x *= inv; v[i].y *= inv; v[i].z *= inv; v[i].w *= inv;
        ((float4*)p)[i * 512 + tid] = v[i];
    }
}

// ------- layernorm over D=512, both branches: out = LN(X (+resid)(+biasVec))*g + b -------
__global__ void layernorm_k(LnB p)
{
    const int row = blockIdx.x;
    const int z = blockIdx.y;
    const int tid = threadIdx.x;
    float4 x = ((const float4*)(p.X[z] + (size_t)row * DD))[tid];
    if (p.resid[z]) {
        float4 r = ((const float4*)(p.resid[z] + (size_t)row * DD))[tid];
        x.x += r.x; x.y += r.y; x.z += r.z; x.w += r.w;
    }
    if (p.biasVec[z]) {
        float4 r = ((const float4*)p.biasVec[z])[tid];
        x.x += r.x; x.y += r.y; x.z += r.z; x.w += r.w;
    }
    float s = x.x + x.y + x.z + x.w;
    s = blockReduceSum(s);
    const float mean = s * (1.0f / DD);
    const float dx = x.x - mean, dy = x.y - mean, dz = x.z - mean, dw = x.w - mean;
    float sq = dx * dx + dy * dy + dz * dz + dw * dw;
    sq = blockReduceSum(sq);
    const float rstd = rsqrtf(sq * (1.0f / DD) + 1e-5f);
    const float4 gg = ((const float4*)p.g[z])[tid];
    const float4 bb = ((const float4*)p.b[z])[tid];
    float4 o;
    o.x = dx * rstd * gg.x + bb.x;
    o.y = dy * rstd * gg.y + bb.y;
    o.z = dz * rstd * gg.z + bb.z;
    o.w = dw * rstd * gg.w + bb.w;
    ((float4*)(p.out[z] + (size_t)row * DD))[tid] = o;
}

// ---------------- host orchestration ----------------
extern "C" void kernel_launch(void* const* d_in, const int* in_sizes, int n_in,
                              void* d_out, int out_size)
{
    (void)in_sizes; (void)n_in; (void)out_size;
    const float* R       = (const float*)d_in[0];
    const float* L       = (const float*)d_in[1];
    const float* Dg      = (const float*)d_in[2];
    const float* De      = (const float*)d_in[3];
    const float* WQ_r    = (const float*)d_in[4];
    const float* WK_r    = (const float*)d_in[5];
    const float* WV_r    = (const float*)d_in[6];
    const float* ln_r1_g = (const float*)d_in[7];
    const float* ln_r1_b = (const float*)d_in[8];
    const float* ffn_r_w1= (const float*)d_in[9];
    const float* ffn_r_b1= (const float*)d_in[10];
    const float* ffn_r_w2= (const float*)d_in[11];
    const float* ffn_r_b2= (const float*)d_in[12];
    const float* ln_r2_g = (const float*)d_in[13];
    const float* ln_r2_b = (const float*)d_in[14];
    const float* WQ_l    = (const float*)d_in[15];
    const float* WK_l    = (const float*)d_in[16];
    const float* WV_l    = (const float*)d_in[17];
    const float* ln_l1_g = (const float*)d_in[18];
    const float* ln_l1_b = (const float*)d_in[19];
    const float* ffn_l_w1= (const float*)d_in[20];
    const float* ffn_l_b1= (const float*)d_in[21];
    const float* ffn_l_w2= (const float*)d_in[22];
    const float* ffn_l_b2= (const float*)d_in[23];
    const float* ln_l2_g = (const float*)d_in[24];
    const float* ln_l2_b = (const float*)d_in[25];

    cudaFuncSetAttribute(gemm_nn_tf32, cudaFuncAttributeMaxDynamicSharedMemorySize, NN_SMEM_BYTES);
    cudaFuncSetAttribute(gemm_nt_tf32, cudaFuncAttributeMaxDynamicSharedMemorySize, NTS_SMEM_BYTES);

    float *QKV, *S2, *X2, *Xn2, *H2;
    cudaGetSymbolAddress((void**)&QKV, g_QKV);
    cudaGetSymbolAddress((void**)&S2,  g_S2);
    cudaGetSymbolAddress((void**)&X2,  g_X2);
    cudaGetSymbolAddress((void**)&Xn2, g_Xn2);
    cudaGetSymbolAddress((void**)&H2,  g_H2);

    float* Qr = QKV + 0 * (size_t)NT * DD;
    float* Kr = QKV + 1 * (size_t)NT * DD;
    float* Vr = QKV + 2 * (size_t)NT * DD;
    float* Ql = QKV + 3 * (size_t)NT * DD;
    float* Kl = QKV + 4 * (size_t)NT * DD;
    float* Vl = QKV + 5 * (size_t)NT * DD;
    float* S0 = S2;
    float* S1 = S2 + (size_t)NT * NT;
    float* X0 = X2,  * X1  = X2  + (size_t)NT * DD;
    float* Xn0 = Xn2, * Xn1 = Xn2 + (size_t)NT * DD;
    float* H0 = H2,  * H1  = H2  + (size_t)NT * DD;
    float* out0 = (float*)d_out;
    float* out1 = out0 + (size_t)NT * DD;

    const dim3 thr(256);
    const float scale = 1.0f / sqrtf((float)DD);

    // 1. all six QKV projections (both branches) in one launch
    {
        GemmB p{};
        p.A[0] = L; p.B[0] = WQ_r; p.C[0] = Qr;   // Q_r = L @ WQ_r
        p.A[1] = R; p.B[1] = WK_r; p.C[1] = Kr;   // K_r = R @ WK_r
        p.A[2] = R; p.B[2] = WV_r; p.C[2] = Vr;   // V_r = R @ WV_r
        p.A[3] = R; p.B[3] = WQ_l; p.C[3] = Ql;   // Q_l = R @ WQ_l
        p.A[4] = L; p.B[4] = WK_l; p.C[4] = Kl;   // K_l = L @ WK_l
        p.A[5] = L; p.B[5] = WV_l; p.C[5] = Vl;   // V_l = L @ WV_l
        gemm_nn_tf32<<<dim3(DD/BN, NT/BM, 6), thr, NN_SMEM_BYTES>>>(p, DD, 0);
    }
    // 2. scores (both branches)
    {
        GemmB p{};
        p.A[0] = Qr; p.B[0] = Kr; p.C[0] = S0;
        p.A[1] = Ql; p.B[1] = Kl; p.C[1] = S1;
        gemm_nt_tf32<<<dim3(NT/BN, NT/BM, 2), thr, NTS_SMEM_BYTES>>>(p, DD, scale);
    }
    // 3. bias + softmax (both branches)
    softmax_bias<<<dim3(NT, 2), 512>>>(S0, S1, De, Dg);
    // 4. att @ V (both branches)
    {
        GemmB p{};
        p.A[0] = S0; p.B[0] = Vr; p.C[0] = X0;
        p.A[1] = S1; p.B[1] = Vl; p.C[1] = X1;
        gemm_nn_tf32<<<dim3(DD/BN, NT/BM, 2), thr, NN_SMEM_BYTES>>>(p, NT, 0);
    }
    // 5. LN1 with residual
    {
        LnB p{};
        p.X[0] = X0; p.resid[0] = R; p.biasVec[0] = nullptr; p.g[0] = ln_r1_g; p.b[0] = ln_r1_b; p.out[0] = Xn0;
        p.X[1] = X1; p.resid[1] = L; p.biasVec[1] = nullptr; p.g[1] = ln_l1_g; p.b[1] = ln_l1_b; p.out[1] = Xn1;
        layernorm_k<<<dim3(NT, 2), 128>>>(p);
    }
    // 6. FFN1 with fused bias+relu epilogue
    {
        GemmB p{};
        p.A[0] = Xn0; p.B[0] = ffn_r_w1; p.C[0] = H0; p.biasVec[0] = ffn_r_b1;
        p.A[1] = Xn1; p.B[1] = ffn_l_w1; p.C[1] = H1; p.biasVec[1] = ffn_l_b1;
        gemm_nn_tf32<<<dim3(DD/BN, NT/BM, 2), thr, NN_SMEM_BYTES>>>(p, DD, 1);
    }
    // 7. FFN2
    {
        GemmB p{};
        p.A[0] = H0; p.B[0] = ffn_r_w2; p.C[0] = X0;
        p.A[1] = H1; p.B[1] = ffn_l_w2; p.C[1] = X1;
        gemm_nn_tf32<<<dim3(DD/BN, NT/BM, 2), thr, NN_SMEM_BYTES>>>(p, DD, 0);
    }
    // 8. LN2: LN(Xn + FFN2out + b2) -> final outputs
    {
        LnB p{};
        p.X[0] = X0; p.resid[0] = Xn0; p.biasVec[0] = ffn_r_b2; p.g[0] = ln_r2_g; p.b[0] = ln_r2_b; p.out[0] = out0;
        p.X[1] = X1; p.resid[1] = Xn1; p.biasVec[1] = ffn_l_b2; p.g[1] = ln_l2_g; p.b[1] = ln_l2_b; p.out[1] = out1;
        layernorm_k<<<dim3(NT, 2), 128>>>(p);
    }
}

// round 10
// speedup vs baseline: 1.0114x; 1.0114x over previous
#include <cuda_runtime.h>
#include <mma.h>
#include <math.h>

using namespace nvcuda;

#define NT 4096
#define DD 512
#define BM 128
#define BN 128
#define BK 16
#define GTHREADS 512

// ---------------- scratch (no cudaMalloc allowed) ----------------
__device__ float g_QKV[6][NT * DD];          // 48 MB
__device__ float g_S2 [2][(size_t)NT * NT];  // 128 MB
__device__ float g_X2 [2][NT * DD];          // 16 MB
__device__ float g_Xn2[2][NT * DD];          // 16 MB
__device__ float g_H2 [2][NT * DD];          // 16 MB

// ---------------- pointer bundles (passed by value) ----------------
struct GemmB {
    const float* A[6];
    const float* B[6];
    float*       C[6];
    const float* biasVec[6];
};
struct LnB {
    const float* X[2];
    const float* resid[2];
    const float* biasVec[2];
    const float* g[2];
    const float* b[2];
    float*       out[2];
};

// ---------------- helpers ----------------
__device__ __forceinline__ void split_store(float x, float* hp, float* lp) {
    float h = wmma::__float_to_tf32(x);
    *hp = h;
    *lp = wmma::__float_to_tf32(x - h);
}

__device__ __forceinline__ float blockReduceSum(float v) {
    __shared__ float sh[32];
    const int lane = threadIdx.x & 31;
    const int warp = threadIdx.x >> 5;
    const int nw = blockDim.x >> 5;
#pragma unroll
    for (int o = 16; o > 0; o >>= 1) v += __shfl_xor_sync(0xffffffffu, v, o);
    __syncthreads();
    if (lane == 0) sh[warp] = v;
    __syncthreads();
    float s = (threadIdx.x < nw) ? sh[threadIdx.x] : 0.0f;
#pragma unroll
    for (int o = 16; o > 0; o >>= 1) s += __shfl_xor_sync(0xffffffffu, s, o);
    if (threadIdx.x == 0) sh[0] = s;
    __syncthreads();
    return sh[0];
}

__device__ __forceinline__ float blockReduceMax(float v) {
    __shared__ float sh[32];
    const int lane = threadIdx.x & 31;
    const int warp = threadIdx.x >> 5;
    const int nw = blockDim.x >> 5;
#pragma unroll
    for (int o = 16; o > 0; o >>= 1) v = fmaxf(v, __shfl_xor_sync(0xffffffffu, v, o));
    __syncthreads();
    if (lane == 0) sh[warp] = v;
    __syncthreads();
    float s = (threadIdx.x < nw) ? sh[threadIdx.x] : -3.402823466e38f;
#pragma unroll
    for (int o = 16; o > 0; o >>= 1) s = fmaxf(s, __shfl_xor_sync(0xffffffffu, s, o));
    if (threadIdx.x == 0) sh[0] = s;
    __syncthreads();
    return sh[0];
}

// ================= batched GEMM NN (split-tf32, double-buffered, 16 warps) =================
// C[z] = A[z][MxK] @ B[z][KxN] (+biasVec[z]) (relu), N=512.
// 128x128 tile, BK=16, 512 thr (16 warps 4x4), warp tile 32x32, wmma 16x16x8,
// hi/lo split => 3 MMAs per product.
// Dynamic smem: Ah/Al[2][128][20], Bh/Bl[2][16][132]  (74752 B)
#define NN_SMEM_FLOATS (2*128*20*2 + 2*16*132*2)
#define NN_SMEM_BYTES (NN_SMEM_FLOATS * 4)

__global__ __launch_bounds__(GTHREADS)
void gemm_nn_tf32(GemmB p, int K, int doRelu)
{
    const int N = DD;
    const float* __restrict__ A = p.A[blockIdx.z];
    const float* __restrict__ B = p.B[blockIdx.z];
    float* __restrict__ C = p.C[blockIdx.z];
    const float* __restrict__ biasVec = p.biasVec[blockIdx.z];

    extern __shared__ float sm[];
    float (*Ah)[128][20] = (float(*)[128][20])(sm);
    float (*Al)[128][20] = (float(*)[128][20])(sm + 2*128*20);
    float (*Bh)[16][132] = (float(*)[16][132])(sm + 4*128*20);
    float (*Bl)[16][132] = (float(*)[16][132])(sm + 4*128*20 + 2*16*132);

    const int tid = threadIdx.x;
    const int bm = blockIdx.y * BM;
    const int bn = blockIdx.x * BN;
    const int warp = tid >> 5;
    const int wm = (warp & 3) * 32;
    const int wn = (warp >> 2) * 32;

    wmma::fragment<wmma::accumulator, 16, 16, 8, float> acc[2][2];
#pragma unroll
    for (int i = 0; i < 2; i++)
#pragma unroll
        for (int j = 0; j < 2; j++) wmma::fill_fragment(acc[i][j], 0.0f);

    const int ar = tid >> 2;            // 0..127
    const int ac = (tid & 3) << 2;      // 0,4,8,12
    const int br = tid >> 5;            // 0..15
    const int bc = (tid & 31) << 2;     // 0..124

    const float* Abase = A + (size_t)(bm + ar) * K + ac;
    const float* Bbase = B + (size_t)br * N + bn + bc;

    const int ntiles = K / BK;

    float4 aR = *(const float4*)Abase;
    float4 bR = *(const float4*)Bbase;
    split_store(aR.x, &Ah[0][ar][ac+0], &Al[0][ar][ac+0]);
    split_store(aR.y, &Ah[0][ar][ac+1], &Al[0][ar][ac+1]);
    split_store(aR.z, &Ah[0][ar][ac+2], &Al[0][ar][ac+2]);
    split_store(aR.w, &Ah[0][ar][ac+3], &Al[0][ar][ac+3]);
    split_store(bR.x, &Bh[0][br][bc+0], &Bl[0][br][bc+0]);
    split_store(bR.y, &Bh[0][br][bc+1], &Bl[0][br][bc+1]);
    split_store(bR.z, &Bh[0][br][bc+2], &Bl[0][br][bc+2]);
    split_store(bR.w, &Bh[0][br][bc+3], &Bl[0][br][bc+3]);
    __syncthreads();

    for (int t = 0; t < ntiles; ++t) {
        const int cur = t & 1;
        const int nxt = cur ^ 1;
        if (t + 1 < ntiles) {
            const int koff = (t + 1) * BK;
            aR = *(const float4*)(Abase + koff);
            bR = *(const float4*)(Bbase + (size_t)koff * N);
        }

#pragma unroll
        for (int kk = 0; kk < BK; kk += 8) {
            wmma::fragment<wmma::matrix_a, 16, 16, 8, wmma::precision::tf32, wmma::row_major> aH[2], aL[2];
            wmma::fragment<wmma::matrix_b, 16, 16, 8, wmma::precision::tf32, wmma::row_major> bH[2], bL[2];
#pragma unroll
            for (int i = 0; i < 2; i++) {
                wmma::load_matrix_sync(aH[i], &Ah[cur][wm + i * 16][kk], 20);
                wmma::load_matrix_sync(aL[i], &Al[cur][wm + i * 16][kk], 20);
            }
#pragma unroll
            for (int j = 0; j < 2; j++) {
                wmma::load_matrix_sync(bH[j], &Bh[cur][kk][wn + j * 16], 132);
                wmma::load_matrix_sync(bL[j], &Bl[cur][kk][wn + j * 16], 132);
            }
#pragma unroll
            for (int i = 0; i < 2; i++)
#pragma unroll
                for (int j = 0; j < 2; j++) {
                    wmma::mma_sync(acc[i][j], aH[i], bH[j], acc[i][j]);
                    wmma::mma_sync(acc[i][j], aH[i], bL[j], acc[i][j]);
                    wmma::mma_sync(acc[i][j], aL[i], bH[j], acc[i][j]);
                }
        }

        if (t + 1 < ntiles) {
            split_store(aR.x, &Ah[nxt][ar][ac+0], &Al[nxt][ar][ac+0]);
            split_store(aR.y, &Ah[nxt][ar][ac+1], &Al[nxt][ar][ac+1]);
            split_store(aR.z, &Ah[nxt][ar][ac+2], &Al[nxt][ar][ac+2]);
            split_store(aR.w, &Ah[nxt][ar][ac+3], &Al[nxt][ar][ac+3]);
            split_store(bR.x, &Bh[nxt][br][bc+0], &Bl[nxt][br][bc+0]);
            split_store(bR.y, &Bh[nxt][br][bc+1], &Bl[nxt][br][bc+1]);
            split_store(bR.z, &Bh[nxt][br][bc+2], &Bl[nxt][br][bc+2]);
            split_store(bR.w, &Bh[nxt][br][bc+3], &Bl[nxt][br][bc+3]);
            __syncthreads();
        }
    }

#pragma unroll
    for (int i = 0; i < 2; i++)
#pragma unroll
        for (int j = 0; j < 2; j++)
            wmma::store_matrix_sync(C + (size_t)(bm + wm + i * 16) * N + bn + wn + j * 16,
                                    acc[i][j], N, wmma::mem_row_major);

    // Fused epilogue: bias (+relu) on the L1/L2-hot C tile (layout-agnostic).
    if (biasVec) {
        __syncthreads();
        const int er = tid >> 2;               // 0..127
        const int ec = (tid & 3) * 32;         // 0,32,64,96
        float* crow = C + (size_t)(bm + er) * N + bn + ec;
        const float* bv = biasVec + bn + ec;
#pragma unroll
        for (int c = 0; c < 32; c += 4) {
            float4 v = *(const float4*)(crow + c);
            float4 b = *(const float4*)(bv + c);
            v.x += b.x; v.y += b.y; v.z += b.z; v.w += b.w;
            if (doRelu) {
                v.x = fmaxf(v.x, 0.0f); v.y = fmaxf(v.y, 0.0f);
                v.z = fmaxf(v.z, 0.0f); v.w = fmaxf(v.w, 0.0f);
            }
            *(float4*)(crow + c) = v;
        }
    }
}

// ================= batched GEMM NT (split-tf32, double-buffered, 16 warps) =================
// C[z] = scale * A[z][MxK] @ B[z][NxK]^T, M=N=4096, K=512.
// Dynamic smem: Ah/Al/Bh/Bl[2][128][20]  (81920 B)
#define NTS_SMEM_FLOATS (4*2*128*20)
#define NTS_SMEM_BYTES (NTS_SMEM_FLOATS * 4)

__global__ __launch_bounds__(GTHREADS)
void gemm_nt_tf32(GemmB p, int K, float scale)
{
    const int N = NT;
    const float* __restrict__ A = p.A[blockIdx.z];
    const float* __restrict__ B = p.B[blockIdx.z];
    float* __restrict__ C = p.C[blockIdx.z];

    extern __shared__ float sm[];
    float (*Ah)[128][20] = (float(*)[128][20])(sm);
    float (*Al)[128][20] = (float(*)[128][20])(sm + 2*128*20);
    float (*Bh)[128][20] = (float(*)[128][20])(sm + 4*128*20);
    float (*Bl)[128][20] = (float(*)[128][20])(sm + 6*128*20);

    const int tid = threadIdx.x;
    const int bm = blockIdx.y * BM;
    const int bn = blockIdx.x * BN;
    const int warp = tid >> 5;
    const int wm = (warp & 3) * 32;
    const int wn = (warp >> 2) * 32;

    wmma::fragment<wmma::accumulator, 16, 16, 8, float> acc[2][2];
#pragma unroll
    for (int i = 0; i < 2; i++)
#pragma unroll
        for (int j = 0; j < 2; j++) wmma::fill_fragment(acc[i][j], 0.0f);

    const int ar = tid >> 2;            // 0..127
    const int ac = (tid & 3) << 2;      // 0,4,8,12

    const float* Abase = A + (size_t)(bm + ar) * K + ac;
    const float* Bbase = B + (size_t)(bn + ar) * K + ac;

    const int ntiles = K / BK;

    float4 aR = *(const float4*)Abase;
    float4 bR = *(const float4*)Bbase;
    split_store(aR.x, &Ah[0][ar][ac+0], &Al[0][ar][ac+0]);
    split_store(aR.y, &Ah[0][ar][ac+1], &Al[0][ar][ac+1]);
    split_store(aR.z, &Ah[0][ar][ac+2], &Al[0][ar][ac+2]);
    split_store(aR.w, &Ah[0][ar][ac+3], &Al[0][ar][ac+3]);
    split_store(bR.x, &Bh[0][ar][ac+0], &Bl[0][ar][ac+0]);
    split_store(bR.y, &Bh[0][ar][ac+1], &Bl[0][ar][ac+1]);
    split_store(bR.z, &Bh[0][ar][ac+2], &Bl[0][ar][ac+2]);
    split_store(bR.w, &Bh[0][ar][ac+3], &Bl[0][ar][ac+3]);
    __syncthreads();

    for (int t = 0; t < ntiles; ++t) {
        const int cur = t & 1;
        const int nxt = cur ^ 1;
        if (t + 1 < ntiles) {
            const int koff = (t + 1) * BK;
            aR = *(const float4*)(Abase + koff);
            bR = *(const float4*)(Bbase + koff);
        }

#pragma unroll
        for (int kk = 0; kk < BK; kk += 8) {
            wmma::fragment<wmma::matrix_a, 16, 16, 8, wmma::precision::tf32, wmma::row_major> aH[2], aL[2];
            wmma::fragment<wmma::matrix_b, 16, 16, 8, wmma::precision::tf32, wmma::col_major> bH[2], bL[2];
#pragma unroll
            for (int i = 0; i < 2; i++) {
                wmma::load_matrix_sync(aH[i], &Ah[cur][wm + i * 16][kk], 20);
                wmma::load_matrix_sync(aL[i], &Al[cur][wm + i * 16][kk], 20);
            }
#pragma unroll
            for (int j = 0; j < 2; j++) {
                wmma::load_matrix_sync(bH[j], &Bh[cur][wn + j * 16][kk], 20);
                wmma::load_matrix_sync(bL[j], &Bl[cur][wn + j * 16][kk], 20);
            }
#pragma unroll
            for (int i = 0; i < 2; i++)
#pragma unroll
                for (int j = 0; j < 2; j++) {
                    wmma::mma_sync(acc[i][j], aH[i], bH[j], acc[i][j]);
                    wmma::mma_sync(acc[i][j], aH[i], bL[j], acc[i][j]);
                    wmma::mma_sync(acc[i][j], aL[i], bH[j], acc[i][j]);
                }
        }

        if (t + 1 < ntiles) {
            split_store(aR.x, &Ah[nxt][ar][ac+0], &Al[nxt][ar][ac+0]);
            split_store(aR.y, &Ah[nxt][ar][ac+1], &Al[nxt][ar][ac+1]);
            split_store(aR.z, &Ah[nxt][ar][ac+2], &Al[nxt][ar][ac+2]);
            split_store(aR.w, &Ah[nxt][ar][ac+3], &Al[nxt][ar][ac+3]);
            split_store(bR.x, &Bh[nxt][ar][ac+0], &Bl[nxt][ar][ac+0]);
            split_store(bR.y, &Bh[nxt][ar][ac+1], &Bl[nxt][ar][ac+1]);
            split_store(bR.z, &Bh[nxt][ar][ac+2], &Bl[nxt][ar][ac+2]);
            split_store(bR.w, &Bh[nxt][ar][ac+3], &Bl[nxt][ar][ac+3]);
            __syncthreads();
        }
    }

#pragma unroll
    for (int i = 0; i < 2; i++)
#pragma unroll
        for (int j = 0; j < 2; j++) {
#pragma unroll
            for (int t = 0; t < acc[i][j].num_elements; t++) acc[i][j].x[t] *= scale;
            wmma::store_matrix_sync(C + (size_t)(bm + wm + i * 16) * N + bn + wn + j * 16,
                                    acc[i][j], N, wmma::mem_row_major);
        }
}

// ------- bias(+transform) + softmax, both branches -------
__global__ void softmax_bias(float* __restrict__ S0, float* __restrict__ S1,
                             const float* __restrict__ De, const float* __restrict__ Dg)
{
    const int row = blockIdx.x;
    const int expMode = (blockIdx.y == 0);
    float* p = (expMode ? S0 : S1) + (size_t)row * NT;
    const float* bp = (expMode ? De : Dg) + (size_t)row * NT;
    const int tid = threadIdx.x;
    float4 v[2];
    float mx = -3.402823466e38f;
#pragma unroll
    for (int i = 0; i < 2; i++) {
        v[i] = ((const float4*)p)[i * 512 + tid];
        float4 b = ((const float4*)bp)[i * 512 + tid];
        if (expMode) {
            v[i].x += __expf(b.x * b.x * (-0.005f));
            v[i].y += __expf(b.y * b.y * (-0.005f));
            v[i].z += __expf(b.z * b.z * (-0.005f));
            v[i].w += __expf(b.w * b.w * (-0.005f));
        } else {
            v[i].x += b.x; v[i].y += b.y; v[i].z += b.z; v[i].w += b.w;
        }
        mx = fmaxf(mx, fmaxf(fmaxf(v[i].x, v[i].y), fmaxf(v[i].z, v[i].w)));
    }
    mx = blockReduceMax(mx);
    float s = 0.0f;
#pragma unroll
    for (int i = 0; i < 2; i++) {
        v[i].x = __expf(v[i].x - mx);
        v[i].y = __expf(v[i].y - mx);
        v[i].z = __expf(v[i].z - mx);
        v[i].w = __expf(v[i].w - mx);
        s += v[i].x + v[i].y + v[i].z + v[i].w;
    }
    s = blockReduceSum(s);
    const float inv = 1.0f / s;
#pragma unroll
    for (int i = 0; i < 2; i++) {
        v[i].x *= inv; v[i].y *= inv; v[i].z *= inv; v[i].w *= inv;
        ((float4*)p)[i * 512 + tid] = v[i];
    }
}

// ------- layernorm over D=512, both branches -------
__global__ void layernorm_k(LnB p)
{
    const int row = blockIdx.x;
    const int z = blockIdx.y;
    const int tid = threadIdx.x;
    float4 x = ((const float4*)(p.X[z] + (size_t)row * DD))[tid];
    if (p.resid[z]) {
        float4 r = ((const float4*)(p.resid[z] + (size_t)row * DD))[tid];
        x.x += r.x; x.y += r.y; x.z += r.z; x.w += r.w;
    }
    if (p.biasVec[z]) {
        float4 r = ((const float4*)p.biasVec[z])[tid];
        x.x += r.x; x.y += r.y; x.z += r.z; x.w += r.w;
    }
    float s = x.x + x.y + x.z + x.w;
    s = blockReduceSum(s);
    const float mean = s * (1.0f / DD);
    const float dx = x.x - mean, dy = x.y - mean, dz = x.z - mean, dw = x.w - mean;
    float sq = dx * dx + dy * dy + dz * dz + dw * dw;
    sq = blockReduceSum(sq);
    const float rstd = rsqrtf(sq * (1.0f / DD) + 1e-5f);
    const float4 gg = ((const float4*)p.g[z])[tid];
    const float4 bb = ((const float4*)p.b[z])[tid];
    float4 o;
    o.x = dx * rstd * gg.x + bb.x;
    o.y = dy * rstd * gg.y + bb.y;
    o.z = dz * rstd * gg.z + bb.z;
    o.w = dw * rstd * gg.w + bb.w;
    ((float4*)(p.out[z] + (size_t)row * DD))[tid] = o;
}

// ---------------- host orchestration ----------------
extern "C" void kernel_launch(void* const* d_in, const int* in_sizes, int n_in,
                              void* d_out, int out_size)
{
    (void)in_sizes; (void)n_in; (void)out_size;
    const float* R       = (const float*)d_in[0];
    const float* L       = (const float*)d_in[1];
    const float* Dg      = (const float*)d_in[2];
    const float* De      = (const float*)d_in[3];
    const float* WQ_r    = (const float*)d_in[4];
    const float* WK_r    = (const float*)d_in[5];
    const float* WV_r    = (const float*)d_in[6];
    const float* ln_r1_g = (const float*)d_in[7];
    const float* ln_r1_b = (const float*)d_in[8];
    const float* ffn_r_w1= (const float*)d_in[9];
    const float* ffn_r_b1= (const float*)d_in[10];
    const float* ffn_r_w2= (const float*)d_in[11];
    const float* ffn_r_b2= (const float*)d_in[12];
    const float* ln_r2_g = (const float*)d_in[13];
    const float* ln_r2_b = (const float*)d_in[14];
    const float* WQ_l    = (const float*)d_in[15];
    const float* WK_l    = (const float*)d_in[16];
    const float* WV_l    = (const float*)d_in[17];
    const float* ln_l1_g = (const float*)d_in[18];
    const float* ln_l1_b = (const float*)d_in[19];
    const float* ffn_l_w1= (const float*)d_in[20];
    const float* ffn_l_b1= (const float*)d_in[21];
    const float* ffn_l_w2= (const float*)d_in[22];
    const float* ffn_l_b2= (const float*)d_in[23];
    const float* ln_l2_g = (const float*)d_in[24];
    const float* ln_l2_b = (const float*)d_in[25];

    cudaFuncSetAttribute(gemm_nn_tf32, cudaFuncAttributeMaxDynamicSharedMemorySize, NN_SMEM_BYTES);
    cudaFuncSetAttribute(gemm_nt_tf32, cudaFuncAttributeMaxDynamicSharedMemorySize, NTS_SMEM_BYTES);

    float *QKV, *S2, *X2, *Xn2, *H2;
    cudaGetSymbolAddress((void**)&QKV, g_QKV);
    cudaGetSymbolAddress((void**)&S2,  g_S2);
    cudaGetSymbolAddress((void**)&X2,  g_X2);
    cudaGetSymbolAddress((void**)&Xn2, g_Xn2);
    cudaGetSymbolAddress((void**)&H2,  g_H2);

    float* Qr = QKV + 0 * (size_t)NT * DD;
    float* Kr = QKV + 1 * (size_t)NT * DD;
    float* Vr = QKV + 2 * (size_t)NT * DD;
    float* Ql = QKV + 3 * (size_t)NT * DD;
    float* Kl = QKV + 4 * (size_t)NT * DD;
    float* Vl = QKV + 5 * (size_t)NT * DD;
    float* S0 = S2;
    float* S1 = S2 + (size_t)NT * NT;
    float* X0 = X2,  * X1  = X2  + (size_t)NT * DD;
    float* Xn0 = Xn2, * Xn1 = Xn2 + (size_t)NT * DD;
    float* H0 = H2,  * H1  = H2  + (size_t)NT * DD;
    float* out0 = (float*)d_out;
    float* out1 = out0 + (size_t)NT * DD;

    const dim3 thr(GTHREADS);
    const float scale = 1.0f / sqrtf((float)DD);

    // 1. all six QKV projections (both branches) in one launch
    {
        GemmB p{};
        p.A[0] = L; p.B[0] = WQ_r; p.C[0] = Qr;
        p.A[1] = R; p.B[1] = WK_r; p.C[1] = Kr;
        p.A[2] = R; p.B[2] = WV_r; p.C[2] = Vr;
        p.A[3] = R; p.B[3] = WQ_l; p.C[3] = Ql;
        p.A[4] = L; p.B[4] = WK_l; p.C[4] = Kl;
        p.A[5] = L; p.B[5] = WV_l; p.C[5] = Vl;
        gemm_nn_tf32<<<dim3(DD/BN, NT/BM, 6), thr, NN_SMEM_BYTES>>>(p, DD, 0);
    }
    // 2. scores (both branches)
    {
        GemmB p{};
        p.A[0] = Qr; p.B[0] = Kr; p.C[0] = S0;
        p.A[1] = Ql; p.B[1] = Kl; p.C[1] = S1;
        gemm_nt_tf32<<<dim3(NT/BN, NT/BM, 2), thr, NTS_SMEM_BYTES>>>(p, DD, scale);
    }
    // 3. bias + softmax (both branches)
    softmax_bias<<<dim3(NT, 2), 512>>>(S0, S1, De, Dg);
    // 4. att @ V (both branches)
    {
        GemmB p{};
        p.A[0] = S0; p.B[0] = Vr; p.C[0] = X0;
        p.A[1] = S1; p.B[1] = Vl; p.C[1] = X1;
        gemm_nn_tf32<<<dim3(DD/BN, NT/BM, 2), thr, NN_SMEM_BYTES>>>(p, NT, 0);
    }
    // 5. LN1 with residual
    {
        LnB p{};
        p.X[0] = X0; p.resid[0] = R; p.biasVec[0] = nullptr; p.g[0] = ln_r1_g; p.b[0] = ln_r1_b; p.out[0] = Xn0;
        p.X[1] = X1; p.resid[1] = L; p.biasVec[1] = nullptr; p.g[1] = ln_l1_g; p.b[1] = ln_l1_b; p.out[1] = Xn1;
        layernorm_k<<<dim3(NT, 2), 128>>>(p);
    }
    // 6. FFN1 with fused bias+relu epilogue
    {
        GemmB p{};
        p.A[0] = Xn0; p.B[0] = ffn_r_w1; p.C[0] = H0; p.biasVec[0] = ffn_r_b1;
        p.A[1] = Xn1; p.B[1] = ffn_l_w1; p.C[1] = H1; p.biasVec[1] = ffn_l_b1;
        gemm_nn_tf32<<<dim3(DD/BN, NT/BM, 2), thr, NN_SMEM_BYTES>>>(p, DD, 1);
    }
    // 7. FFN2
    {
        GemmB p{};
        p.A[0] = H0; p.B[0] = ffn_r_w2; p.C[0] = X0;
        p.A[1] = H1; p.B[1] = ffn_l_w2; p.C[1] = X1;
        gemm_nn_tf32<<<dim3(DD/BN, NT/BM, 2), thr, NN_SMEM_BYTES>>>(p, DD, 0);
    }
    // 8. LN2: LN(Xn + FFN2out + b2) -> final outputs
    {
        LnB p{};
        p.X[0] = X0; p.resid[0] = Xn0; p.biasVec[0] = ffn_r_b2; p.g[0] = ln_r2_g; p.b[0] = ln_r2_b; p.out[0] = out0;
        p.X[1] = X1; p.resid[1] = Xn1; p.biasVec[1] = ffn_l_b2; p.g[1] = ln_l2_g; p.b[1] = ln_l2_b; p.out[1] = out1;
        layernorm_k<<<dim3(NT, 2), 128>>>(p);
    }
}

// round 14
// speedup vs baseline: 1.3239x; 1.3090x over previous
#include <cuda_runtime.h>
#include <mma.h>
#include <math.h>

using namespace nvcuda;

#define NT 4096
#define DD 512
#define BM 128
#define BN 128
#define BK 16
#define GTHREADS 512

// ---------------- scratch (no cudaMalloc allowed) ----------------
__device__ float g_QKV[6][NT * DD];          // 48 MB
__device__ float g_S2 [2][(size_t)NT * NT];  // 128 MB
__device__ float g_X2 [2][NT * DD];          // 16 MB
__device__ float g_Xn2[2][NT * DD];          // 16 MB
__device__ float g_H2 [2][NT * DD];          // 16 MB

// ---------------- pointer bundles (passed by value) ----------------
struct GemmB {
    const float* A[6];
    const float* B[6];
    float*       C[6];
    const float* biasVec[6];
};
struct LnB {
    const float* X[2];
    const float* resid[2];
    const float* biasVec[2];
    const float* g[2];
    const float* b[2];
    float*       out[2];
};

// ---------------- helpers ----------------
__device__ __forceinline__ void split_store(float x, float* hp, float* lp) {
    float h = wmma::__float_to_tf32(x);
    *hp = h;
    *lp = wmma::__float_to_tf32(x - h);
}

__device__ __forceinline__ float blockReduceSum(float v) {
    __shared__ float sh[32];
    const int lane = threadIdx.x & 31;
    const int warp = threadIdx.x >> 5;
    const int nw = blockDim.x >> 5;
#pragma unroll
    for (int o = 16; o > 0; o >>= 1) v += __shfl_xor_sync(0xffffffffu, v, o);
    __syncthreads();
    if (lane == 0) sh[warp] = v;
    __syncthreads();
    float s = (threadIdx.x < nw) ? sh[threadIdx.x] : 0.0f;
#pragma unroll
    for (int o = 16; o > 0; o >>= 1) s += __shfl_xor_sync(0xffffffffu, s, o);
    if (threadIdx.x == 0) sh[0] = s;
    __syncthreads();
    return sh[0];
}

__device__ __forceinline__ float blockReduceMax(float v) {
    __shared__ float sh[32];
    const int lane = threadIdx.x & 31;
    const int warp = threadIdx.x >> 5;
    const int nw = blockDim.x >> 5;
#pragma unroll
    for (int o = 16; o > 0; o >>= 1) v = fmaxf(v, __shfl_xor_sync(0xffffffffu, v, o));
    __syncthreads();
    if (lane == 0) sh[warp] = v;
    __syncthreads();
    float s = (threadIdx.x < nw) ? sh[threadIdx.x] : -3.402823466e38f;
#pragma unroll
    for (int o = 16; o > 0; o >>= 1) s = fmaxf(s, __shfl_xor_sync(0xffffffffu, s, o));
    if (threadIdx.x == 0) sh[0] = s;
    __syncthreads();
    return sh[0];
}

// ================= batched GEMM NN (asym split-tf32: A rounded, B split) =================
// C[z] = A[z][MxK] @ B[z][KxN] (+biasVec[z]) (relu), N=512.
// 128x128 tile, BK=16, 512 thr (16 warps 4x4), warp tile 32x32, wmma 16x16x8,
// 2 MMAs per product: aH*bH + aH*bL.
// Dynamic smem: Ah[2][128][20], Bh/Bl[2][16][132]  (54272 B)
#define NN_SMEM_FLOATS (2*128*20 + 2*16*132*2)
#define NN_SMEM_BYTES (NN_SMEM_FLOATS * 4)

__global__ __launch_bounds__(GTHREADS)
void gemm_nn_tf32(GemmB p, int K, int doRelu)
{
    const int N = DD;
    const float* __restrict__ A = p.A[blockIdx.z];
    const float* __restrict__ B = p.B[blockIdx.z];
    float* __restrict__ C = p.C[blockIdx.z];
    const float* __restrict__ biasVec = p.biasVec[blockIdx.z];

    extern __shared__ float sm[];
    float (*Ah)[128][20] = (float(*)[128][20])(sm);
    float (*Bh)[16][132] = (float(*)[16][132])(sm + 2*128*20);
    float (*Bl)[16][132] = (float(*)[16][132])(sm + 2*128*20 + 2*16*132);

    const int tid = threadIdx.x;
    const int bm = blockIdx.y * BM;
    const int bn = blockIdx.x * BN;
    const int warp = tid >> 5;
    const int wm = (warp & 3) * 32;
    const int wn = (warp >> 2) * 32;

    wmma::fragment<wmma::accumulator, 16, 16, 8, float> acc[2][2];
#pragma unroll
    for (int i = 0; i < 2; i++)
#pragma unroll
        for (int j = 0; j < 2; j++) wmma::fill_fragment(acc[i][j], 0.0f);

    const int ar = tid >> 2;            // 0..127
    const int ac = (tid & 3) << 2;      // 0,4,8,12
    const int br = tid >> 5;            // 0..15
    const int bc = (tid & 31) << 2;     // 0..124

    const float* Abase = A + (size_t)(bm + ar) * K + ac;
    const float* Bbase = B + (size_t)br * N + bn + bc;

    const int ntiles = K / BK;

    float4 aR = *(const float4*)Abase;
    float4 bR = *(const float4*)Bbase;
    Ah[0][ar][ac+0] = wmma::__float_to_tf32(aR.x);
    Ah[0][ar][ac+1] = wmma::__float_to_tf32(aR.y);
    Ah[0][ar][ac+2] = wmma::__float_to_tf32(aR.z);
    Ah[0][ar][ac+3] = wmma::__float_to_tf32(aR.w);
    split_store(bR.x, &Bh[0][br][bc+0], &Bl[0][br][bc+0]);
    split_store(bR.y, &Bh[0][br][bc+1], &Bl[0][br][bc+1]);
    split_store(bR.z, &Bh[0][br][bc+2], &Bl[0][br][bc+2]);
    split_store(bR.w, &Bh[0][br][bc+3], &Bl[0][br][bc+3]);
    __syncthreads();

    for (int t = 0; t < ntiles; ++t) {
        const int cur = t & 1;
        const int nxt = cur ^ 1;
        if (t + 1 < ntiles) {
            const int koff = (t + 1) * BK;
            aR = *(const float4*)(Abase + koff);
            bR = *(const float4*)(Bbase + (size_t)koff * N);
        }

#pragma unroll
        for (int kk = 0; kk < BK; kk += 8) {
            wmma::fragment<wmma::matrix_a, 16, 16, 8, wmma::precision::tf32, wmma::row_major> aH[2];
            wmma::fragment<wmma::matrix_b, 16, 16, 8, wmma::precision::tf32, wmma::row_major> bH[2], bL[2];
#pragma unroll
            for (int i = 0; i < 2; i++)
                wmma::load_matrix_sync(aH[i], &Ah[cur][wm + i * 16][kk], 20);
#pragma unroll
            for (int j = 0; j < 2; j++) {
                wmma::load_matrix_sync(bH[j], &Bh[cur][kk][wn + j * 16], 132);
                wmma::load_matrix_sync(bL[j], &Bl[cur][kk][wn + j * 16], 132);
            }
#pragma unroll
            for (int i = 0; i < 2; i++)
#pragma unroll
                for (int j = 0; j < 2; j++) {
                    wmma::mma_sync(acc[i][j], aH[i], bH[j], acc[i][j]);
                    wmma::mma_sync(acc[i][j], aH[i], bL[j], acc[i][j]);
                }
        }

        if (t + 1 < ntiles) {
            Ah[nxt][ar][ac+0] = wmma::__float_to_tf32(aR.x);
            Ah[nxt][ar][ac+1] = wmma::__float_to_tf32(aR.y);
            Ah[nxt][ar][ac+2] = wmma::__float_to_tf32(aR.z);
            Ah[nxt][ar][ac+3] = wmma::__float_to_tf32(aR.w);
            split_store(bR.x, &Bh[nxt][br][bc+0], &Bl[nxt][br][bc+0]);
            split_store(bR.y, &Bh[nxt][br][bc+1], &Bl[nxt][br][bc+1]);
            split_store(bR.z, &Bh[nxt][br][bc+2], &Bl[nxt][br][bc+2]);
            split_store(bR.w, &Bh[nxt][br][bc+3], &Bl[nxt][br][bc+3]);
            __syncthreads();
        }
    }

#pragma unroll
    for (int i = 0; i < 2; i++)
#pragma unroll
        for (int j = 0; j < 2; j++)
            wmma::store_matrix_sync(C + (size_t)(bm + wm + i * 16) * N + bn + wn + j * 16,
                                    acc[i][j], N, wmma::mem_row_major);

    // Fused epilogue: bias (+relu) on the L1/L2-hot C tile (layout-agnostic).
    if (biasVec) {
        __syncthreads();
        const int er = tid >> 2;               // 0..127
        const int ec = (tid & 3) * 32;         // 0,32,64,96
        float* crow = C + (size_t)(bm + er) * N + bn + ec;
        const float* bv = biasVec + bn + ec;
#pragma unroll
        for (int c = 0; c < 32; c += 4) {
            float4 v = *(const float4*)(crow + c);
            float4 b = *(const float4*)(bv + c);
            v.x += b.x; v.y += b.y; v.z += b.z; v.w += b.w;
            if (doRelu) {
                v.x = fmaxf(v.x, 0.0f); v.y = fmaxf(v.y, 0.0f);
                v.z = fmaxf(v.z, 0.0f); v.w = fmaxf(v.w, 0.0f);
            }
            *(float4*)(crow + c) = v;
        }
    }
}

// ================= batched GEMM NT (asym split-tf32: A rounded, B split) =================
// C[z] = scale * A[z][MxK] @ B[z][NxK]^T, M=N=4096, K=512.
// Dynamic smem: Ah/Bh/Bl[2][128][20]  (61440 B)
#define NTS_SMEM_FLOATS (3*2*128*20)
#define NTS_SMEM_BYTES (NTS_SMEM_FLOATS * 4)

__global__ __launch_bounds__(GTHREADS)
void gemm_nt_tf32(GemmB p, int K, float scale)
{
    const int N = NT;
    const float* __restrict__ A = p.A[blockIdx.z];
    const float* __restrict__ B = p.B[blockIdx.z];
    float* __restrict__ C = p.C[blockIdx.z];

    extern __shared__ float sm[];
    float (*Ah)[128][20] = (float(*)[128][20])(sm);
    float (*Bh)[128][20] = (float(*)[128][20])(sm + 2*128*20);
    float (*Bl)[128][20] = (float(*)[128][20])(sm + 4*128*20);

    const int tid = threadIdx.x;
    const int bm = blockIdx.y * BM;
    const int bn = blockIdx.x * BN;
    const int warp = tid >> 5;
    const int wm = (warp & 3) * 32;
    const int wn = (warp >> 2) * 32;

    wmma::fragment<wmma::accumulator, 16, 16, 8, float> acc[2][2];
#pragma unroll
    for (int i = 0; i < 2; i++)
#pragma unroll
        for (int j = 0; j < 2; j++) wmma::fill_fragment(acc[i][j], 0.0f);

    const int ar = tid >> 2;            // 0..127
    const int ac = (tid & 3) << 2;      // 0,4,8,12

    const float* Abase = A + (size_t)(bm + ar) * K + ac;
    const float* Bbase = B + (size_t)(bn + ar) * K + ac;

    const int ntiles = K / BK;

    float4 aR = *(const float4*)Abase;
    float4 bR = *(const float4*)Bbase;
    Ah[0][ar][ac+0] = wmma::__float_to_tf32(aR.x);
    Ah[0][ar][ac+1] = wmma::__float_to_tf32(aR.y);
    Ah[0][ar][ac+2] = wmma::__float_to_tf32(aR.z);
    Ah[0][ar][ac+3] = wmma::__float_to_tf32(aR.w);
    split_store(bR.x, &Bh[0][ar][ac+0], &Bl[0][ar][ac+0]);
    split_store(bR.y, &Bh[0][ar][ac+1], &Bl[0][ar][ac+1]);
    split_store(bR.z, &Bh[0][ar][ac+2], &Bl[0][ar][ac+2]);
    split_store(bR.w, &Bh[0][ar][ac+3], &Bl[0][ar][ac+3]);
    __syncthreads();

    for (int t = 0; t < ntiles; ++t) {
        const int cur = t & 1;
        const int nxt = cur ^ 1;
        if (t + 1 < ntiles) {
            const int koff = (t + 1) * BK;
            aR = *(const float4*)(Abase + koff);
            bR = *(const float4*)(Bbase + koff);
        }

#pragma unroll
        for (int kk = 0; kk < BK; kk += 8) {
            wmma::fragment<wmma::matrix_a, 16, 16, 8, wmma::precision::tf32, wmma::row_major> aH[2];
            wmma::fragment<wmma::matrix_b, 16, 16, 8, wmma::precision::tf32, wmma::col_major> bH[2], bL[2];
#pragma unroll
            for (int i = 0; i < 2; i++)
                wmma::load_matrix_sync(aH[i], &Ah[cur][wm + i * 16][kk], 20);
#pragma unroll
            for (int j = 0; j < 2; j++) {
                wmma::load_matrix_sync(bH[j], &Bh[cur][wn + j * 16][kk], 20);
                wmma::load_matrix_sync(bL[j], &Bl[cur][wn + j * 16][kk], 20);
            }
#pragma unroll
            for (int i = 0; i < 2; i++)
#pragma unroll
                for (int j = 0; j < 2; j++) {
                    wmma::mma_sync(acc[i][j], aH[i], bH[j], acc[i][j]);
                    wmma::mma_sync(acc[i][j], aH[i], bL[j], acc[i][j]);
                }
        }

        if (t + 1 < ntiles) {
            Ah[nxt][ar][ac+0] = wmma::__float_to_tf32(aR.x);
            Ah[nxt][ar][ac+1] = wmma::__float_to_tf32(aR.y);
            Ah[nxt][ar][ac+2] = wmma::__float_to_tf32(aR.z);
            Ah[nxt][ar][ac+3] = wmma::__float_to_tf32(aR.w);
            split_store(bR.x, &Bh[nxt][ar][ac+0], &Bl[nxt][ar][ac+0]);
            split_store(bR.y, &Bh[nxt][ar][ac+1], &Bl[nxt][ar][ac+1]);
            split_store(bR.z, &Bh[nxt][ar][ac+2], &Bl[nxt][ar][ac+2]);
            split_store(bR.w, &Bh[nxt][ar][ac+3], &Bl[nxt][ar][ac+3]);
            __syncthreads();
        }
    }

#pragma unroll
    for (int i = 0; i < 2; i++)
#pragma unroll
        for (int j = 0; j < 2; j++) {
#pragma unroll
            for (int t = 0; t < acc[i][j].num_elements; t++) acc[i][j].x[t] *= scale;
            wmma::store_matrix_sync(C + (size_t)(bm + wm + i * 16) * N + bn + wn + j * 16,
                                    acc[i][j], N, wmma::mem_row_major);
        }
}

// ------- bias(+transform) + softmax, both branches -------
__global__ void softmax_bias(float* __restrict__ S0, float* __restrict__ S1,
                             const float* __restrict__ De, const float* __restrict__ Dg)
{
    const int row = blockIdx.x;
    const int expMode = (blockIdx.y == 0);
    float* p = (expMode ? S0 : S1) + (size_t)row * NT;
    const float* bp = (expMode ? De : Dg) + (size_t)row * NT;
    const int tid = threadIdx.x;
    float4 v[2];
    float mx = -3.402823466e38f;
#pragma unroll
    for (int i = 0; i < 2; i++) {
        v[i] = ((const float4*)p)[i * 512 + tid];
        float4 b = ((const float4*)bp)[i * 512 + tid];
        if (expMode) {
            v[i].x += __expf(b.x * b.x * (-0.005f));
            v[i].y += __expf(b.y * b.y * (-0.005f));
            v[i].z += __expf(b.z * b.z * (-0.005f));
            v[i].w += __expf(b.w * b.w * (-0.005f));
        } else {
            v[i].x += b.x; v[i].y += b.y; v[i].z += b.z; v[i].w += b.w;
        }
        mx = fmaxf(mx, fmaxf(fmaxf(v[i].x, v[i].y), fmaxf(v[i].z, v[i].w)));
    }
    mx = blockReduceMax(mx);
    float s = 0.0f;
#pragma unroll
    for (int i = 0; i < 2; i++) {
        v[i].x = __expf(v[i].x - mx);
        v[i].y = __expf(v[i].y - mx);
        v[i].z = __expf(v[i].z - mx);
        v[i].w = __expf(v[i].w - mx);
        s += v[i].x + v[i].y + v[i].z + v[i].w;
    }
    s = blockReduceSum(s);
    const float inv = 1.0f / s;
#pragma unroll
    for (int i = 0; i < 2; i++) {
        v[i].x *= inv; v[i].y *= inv; v[i].z *= inv; v[i].w *= inv;
        ((float4*)p)[i * 512 + tid] = v[i];
    }
}

// ------- layernorm over D=512, both branches -------
__global__ void layernorm_k(LnB p)
{
    const int row = blockIdx.x;
    const int z = blockIdx.y;
    const int tid = threadIdx.x;
    float4 x = ((const float4*)(p.X[z] + (size_t)row * DD))[tid];
    if (p.resid[z]) {
        float4 r = ((const float4*)(p.resid[z] + (size_t)row * DD))[tid];
        x.x += r.x; x.y += r.y; x.z += r.z; x.w += r.w;
    }
    if (p.biasVec[z]) {
        float4 r = ((const float4*)p.biasVec[z])[tid];
        x.x += r.x; x.y += r.y; x.z += r.z; x.w += r.w;
    }
    float s = x.x + x.y + x.z + x.w;
    s = blockReduceSum(s);
    const float mean = s * (1.0f / DD);
    const float dx = x.x - mean, dy = x.y - mean, dz = x.z - mean, dw = x.w - mean;
    float sq = dx * dx + dy * dy + dz * dz + dw * dw;
    sq = blockReduceSum(sq);
    const float rstd = rsqrtf(sq * (1.0f / DD) + 1e-5f);
    const float4 gg = ((const float4*)p.g[z])[tid];
    const float4 bb = ((const float4*)p.b[z])[tid];
    float4 o;
    o.x = dx * rstd * gg.x + bb.x;
    o.y = dy * rstd * gg.y + bb.y;
    o.z = dz * rstd * gg.z + bb.z;
    o.w = dw * rstd * gg.w + bb.w;
    ((float4*)(p.out[z] + (size_t)row * DD))[tid] = o;
}

// ---------------- host orchestration ----------------
extern "C" void kernel_launch(void* const* d_in, const int* in_sizes, int n_in,
                              void* d_out, int out_size)
{
    (void)in_sizes; (void)n_in; (void)out_size;
    const float* R       = (const float*)d_in[0];
    const float* L       = (const float*)d_in[1];
    const float* Dg      = (const float*)d_in[2];
    const float* De      = (const float*)d_in[3];
    const float* WQ_r    = (const float*)d_in[4];
    const float* WK_r    = (const float*)d_in[5];
    const float* WV_r    = (const float*)d_in[6];
    const float* ln_r1_g = (const float*)d_in[7];
    const float* ln_r1_b = (const float*)d_in[8];
    const float* ffn_r_w1= (const float*)d_in[9];
    const float* ffn_r_b1= (const float*)d_in[10];
    const float* ffn_r_w2= (const float*)d_in[11];
    const float* ffn_r_b2= (const float*)d_in[12];
    const float* ln_r2_g = (const float*)d_in[13];
    const float* ln_r2_b = (const float*)d_in[14];
    const float* WQ_l    = (const float*)d_in[15];
    const float* WK_l    = (const float*)d_in[16];
    const float* WV_l    = (const float*)d_in[17];
    const float* ln_l1_g = (const float*)d_in[18];
    const float* ln_l1_b = (const float*)d_in[19];
    const float* ffn_l_w1= (const float*)d_in[20];
    const float* ffn_l_b1= (const float*)d_in[21];
    const float* ffn_l_w2= (const float*)d_in[22];
    const float* ffn_l_b2= (const float*)d_in[23];
    const float* ln_l2_g = (const float*)d_in[24];
    const float* ln_l2_b = (const float*)d_in[25];

    cudaFuncSetAttribute(gemm_nn_tf32, cudaFuncAttributeMaxDynamicSharedMemorySize, NN_SMEM_BYTES);
    cudaFuncSetAttribute(gemm_nt_tf32, cudaFuncAttributeMaxDynamicSharedMemorySize, NTS_SMEM_BYTES);

    float *QKV, *S2, *X2, *Xn2, *H2;
    cudaGetSymbolAddress((void**)&QKV, g_QKV);
    cudaGetSymbolAddress((void**)&S2,  g_S2);
    cudaGetSymbolAddress((void**)&X2,  g_X2);
    cudaGetSymbolAddress((void**)&Xn2, g_Xn2);
    cudaGetSymbolAddress((void**)&H2,  g_H2);

    float* Qr = QKV + 0 * (size_t)NT * DD;
    float* Kr = QKV + 1 * (size_t)NT * DD;
    float* Vr = QKV + 2 * (size_t)NT * DD;
    float* Ql = QKV + 3 * (size_t)NT * DD;
    float* Kl = QKV + 4 * (size_t)NT * DD;
    float* Vl = QKV + 5 * (size_t)NT * DD;
    float* S0 = S2;
    float* S1 = S2 + (size_t)NT * NT;
    float* X0 = X2,  * X1  = X2  + (size_t)NT * DD;
    float* Xn0 = Xn2, * Xn1 = Xn2 + (size_t)NT * DD;
    float* H0 = H2,  * H1  = H2  + (size_t)NT * DD;
    float* out0 = (float*)d_out;
    float* out1 = out0 + (size_t)NT * DD;

    const dim3 thr(GTHREADS);
    const float scale = 1.0f / sqrtf((float)DD);

    // 1. all six QKV projections (both branches) in one launch
    {
        GemmB p{};
        p.A[0] = L; p.B[0] = WQ_r; p.C[0] = Qr;
        p.A[1] = R; p.B[1] = WK_r; p.C[1] = Kr;
        p.A[2] = R; p.B[2] = WV_r; p.C[2] = Vr;
        p.A[3] = R; p.B[3] = WQ_l; p.C[3] = Ql;
        p.A[4] = L; p.B[4] = WK_l; p.C[4] = Kl;
        p.A[5] = L; p.B[5] = WV_l; p.C[5] = Vl;
        gemm_nn_tf32<<<dim3(DD/BN, NT/BM, 6), thr, NN_SMEM_BYTES>>>(p, DD, 0);
    }
    // 2. scores (both branches)
    {
        GemmB p{};
        p.A[0] = Qr; p.B[0] = Kr; p.C[0] = S0;
        p.A[1] = Ql; p.B[1] = Kl; p.C[1] = S1;
        gemm_nt_tf32<<<dim3(NT/BN, NT/BM, 2), thr, NTS_SMEM_BYTES>>>(p, DD, scale);
    }
    // 3. bias + softmax (both branches)
    softmax_bias<<<dim3(NT, 2), 512>>>(S0, S1, De, Dg);
    // 4. att @ V (both branches)
    {
        GemmB p{};
        p.A[0] = S0; p.B[0] = Vr; p.C[0] = X0;
        p.A[1] = S1; p.B[1] = Vl; p.C[1] = X1;
        gemm_nn_tf32<<<dim3(DD/BN, NT/BM, 2), thr, NN_SMEM_BYTES>>>(p, NT, 0);
    }
    // 5. LN1 with residual
    {
        LnB p{};
        p.X[0] = X0; p.resid[0] = R; p.biasVec[0] = nullptr; p.g[0] = ln_r1_g; p.b[0] = ln_r1_b; p.out[0] = Xn0;
        p.X[1] = X1; p.resid[1] = L; p.biasVec[1] = nullptr; p.g[1] = ln_l1_g; p.b[1] = ln_l1_b; p.out[1] = Xn1;
        layernorm_k<<<dim3(NT, 2), 128>>>(p);
    }
    // 6. FFN1 with fused bias+relu epilogue
    {
        GemmB p{};
        p.A[0] = Xn0; p.B[0] = ffn_r_w1; p.C[0] = H0; p.biasVec[0] = ffn_r_b1;
        p.A[1] = Xn1; p.B[1] = ffn_l_w1; p.C[1] = H1; p.biasVec[1] = ffn_l_b1;
        gemm_nn_tf32<<<dim3(DD/BN, NT/BM, 2), thr, NN_SMEM_BYTES>>>(p, DD, 1);
    }
    // 7. FFN2
    {
        GemmB p{};
        p.A[0] = H0; p.B[0] = ffn_r_w2; p.C[0] = X0;
        p.A[1] = H1; p.B[1] = ffn_l_w2; p.C[1] = X1;
        gemm_nn_tf32<<<dim3(DD/BN, NT/BM, 2), thr, NN_SMEM_BYTES>>>(p, DD, 0);
    }
    // 8. LN2: LN(Xn + FFN2out + b2) -> final outputs
    {
        LnB p{};
        p.X[0] = X0; p.resid[0] = Xn0; p.biasVec[0] = ffn_r_b2; p.g[0] = ln_r2_g; p.b[0] = ln_r2_b; p.out[0] = out0;
        p.X[1] = X1; p.resid[1] = Xn1; p.biasVec[1] = ffn_l_b2; p.g[1] = ln_l2_g; p.b[1] = ln_l2_b; p.out[1] = out1;
        layernorm_k<<<dim3(NT, 2), 128>>>(p);
    }
}